// round 1
// baseline (speedup 1.0000x reference)
#include <cuda_runtime.h>
#include <math.h>

#define NFFT      512
#define NH        256          // complex IFFT size
#define HOP       128
#define T_FRAMES  2048
#define F_BINS    257
#define OUT_LEN   262016       // (T-1)*HOP
#define CHUNK     2048         // output samples per block (= 16 hops)
#define MAXFR     19           // frames touching one chunk (16 + 3)
#define OA_LEN    2816         // 128*18 + 512
#define NBC       32           // B*C

struct Smem {
    float2 stage[MAXFR * F_BINS]; // staged spectra [t_rel][k]      39064 B
    float  oa[2][OA_LEN];         // per-group overlap-add          22528 B
    float2 zbuf[2][2][NH];        // per-group ping-pong FFT bufs    8192 B
    float2 e512[NFFT];            // e^{+i 2 pi t / 512}             4096 B
    float  win[NFFT];             // window                          2048 B
};

__device__ __forceinline__ void group_sync(int g) {
    asm volatile("bar.sync %0, 128;" :: "r"(g + 1) : "memory");
}

__global__ void __launch_bounds__(256, 2)
istft_kernel(const float* __restrict__ X,
             const float* __restrict__ window,
             float* __restrict__ out)
{
    extern __shared__ char smraw[];
    Smem& sm = *reinterpret_cast<Smem*>(smraw);

    const int tid = threadIdx.x;      // 0..255
    const int bc  = blockIdx.y;       // 0..31
    const int blk = blockIdx.x;       // 0..127
    const int o0  = blk * CHUNK;

    int t_lo = (o0 - 128) >> 7; if (t_lo < 0) t_lo = 0;
    int t_hi = (o0 + CHUNK + 255) >> 7; if (t_hi > T_FRAMES - 1) t_hi = T_FRAMES - 1;
    const int nt = t_hi - t_lo + 1;   // <= 19

    // ---- tables + OA clear ----
    for (int i = tid; i < NFFT; i += 256) {
        float s, c;
        sincosf((float)(2.0 * M_PI / NFFT) * (float)i, &s, &c);
        sm.e512[i] = make_float2(c, s);
        sm.win[i]  = window[i];
    }
    for (int i = tid; i < 2 * OA_LEN; i += 256)
        (&sm.oa[0][0])[i] = 0.0f;

    // ---- stage spectra: one warp per k-row, lanes sweep the nt frames ----
    // X viewed as float2[(bc*F + k)*T + t]
    const float2* Xbc = reinterpret_cast<const float2*>(X)
                        + (size_t)bc * F_BINS * T_FRAMES;
    {
        const int warp = tid >> 5, lane = tid & 31;
        for (int k = warp; k < F_BINS; k += 8) {
            if (lane < nt)
                sm.stage[lane * F_BINS + k] = Xbc[(size_t)k * T_FRAMES + t_lo + lane];
        }
    }
    __syncthreads();

    // ---- per-group frame processing (group 0: even t_rel, group 1: odd) ----
    const int g  = tid >> 7;          // 0/1
    const int gt = tid & 127;
    float*  oa = sm.oa[g];
    float2* z0 = sm.zbuf[g][0];
    float2* z1 = sm.zbuf[g][1];
    const float inv256 = 1.0f / 256.0f;

    for (int fr = g; fr < nt; fr += 2) {
        const float2* spec = &sm.stage[fr * F_BINS];

        // preprocess: build Z[k] for k = gt, gt+128
        #pragma unroll
        for (int h = 0; h < 2; h++) {
            const int k = gt + 128 * h;
            float2 a = spec[k];
            float2 b = spec[256 - k];
            if (k == 0) { a.y = 0.0f; b.y = 0.0f; }  // irfft ignores imag of DC/Nyquist
            const float zer = 0.5f * (a.x + b.x);
            const float zei = 0.5f * (a.y - b.y);
            const float tr  = 0.5f * (a.x - b.x);
            const float ti  = 0.5f * (a.y + b.y);
            const float2 w  = sm.e512[k];            // e^{+i 2 pi k / 512}
            const float zor = w.x * tr - w.y * ti;
            const float zoi = w.x * ti + w.y * tr;
            z0[k] = make_float2(zer - zoi, zei + zor);
        }
        group_sync(g);

        // 8 radix-2 Stockham stages (IFFT sign, unnormalized)
        float2* src = z0;
        float2* dst = z1;
        #pragma unroll
        for (int s = 0; s < 8; s++) {
            const int m  = 1 << s;
            const int j  = gt >> s;
            const int kk = gt & (m - 1);
            const float2 a = src[gt];
            const float2 b = src[gt + 128];
            const float2 w = sm.e512[(j << (s + 1)) & (NFFT - 1)];
            const float dr = a.x - b.x, di = a.y - b.y;
            const int o = kk + (j << (s + 1));
            dst[o]     = make_float2(a.x + b.x, a.y + b.y);
            dst[o + m] = make_float2(w.x * dr - w.y * di, w.x * di + w.y * dr);
            float2* tpt = src; src = dst; dst = tpt;
            group_sync(g);
        }
        // after 8 swaps result is back in z0 (== src)

        // window * 1/256, overlap-add
        const int obase = fr * HOP;
        #pragma unroll
        for (int h = 0; h < 2; h++) {
            const int n = gt + 128 * h;
            const float2 zz = src[n];
            oa[obase + 2 * n]     += zz.x * sm.win[2 * n]     * inv256;
            oa[obase + 2 * n + 1] += zz.y * sm.win[2 * n + 1] * inv256;
        }
        group_sync(g);  // z0 is rewritten by next frame's preprocess
    }

    __syncthreads();

    // ---- envelope normalize + write ----
    float* outbc = out + (size_t)bc * OUT_LEN;
    const int oabase = t_lo * HOP;
    for (int jj = tid; jj < CHUNK; jj += 256) {
        const int j = o0 + jj;
        if (j >= OUT_LEN) break;
        const int i  = j + NFFT / 2;  // full (untrimmed) index
        const int r  = i & (HOP - 1);
        const int bt = i >> 7;
        float env = 0.0f;
        #pragma unroll
        for (int s2 = 0; s2 < 4; s2++) {
            const int t = bt - s2;
            if (t >= 0 && t <= T_FRAMES - 1) {
                const float wv = sm.win[r + 128 * s2];
                env += wv * wv;
            }
        }
        const float v = sm.oa[0][i - oabase] + sm.oa[1][i - oabase];
        outbc[j] = __fdividef(v, env);
    }
}

extern "C" void kernel_launch(void* const* d_in, const int* in_sizes, int n_in,
                              void* d_out, int out_size)
{
    const float* X   = (const float*)d_in[0];
    const float* win = (const float*)d_in[1];
    float* out       = (float*)d_out;

    // > 48 KB dynamic shared memory: opt in every call (idempotent, capture-safe)
    cudaFuncSetAttribute(istft_kernel,
                         cudaFuncAttributeMaxDynamicSharedMemorySize,
                         (int)sizeof(Smem));

    dim3 grid(OUT_LEN / CHUNK + ((OUT_LEN % CHUNK) ? 1 : 0), NBC);  // (128, 32)
    istft_kernel<<<grid, 256, sizeof(Smem)>>>(X, win, out);
}

// round 2
// speedup vs baseline: 1.0681x; 1.0681x over previous
#include <cuda_runtime.h>
#include <math.h>

#define NFFT      512
#define HOP       128
#define T_FRAMES  2048
#define F_BINS    257
#define OUT_LEN   262016       // (T-1)*HOP
#define CHUNK     2048         // output samples per block (= 16 hops)
#define MAXFR     19           // frames touching one chunk
#define OA_LEN    2816         // 128*18 + 512
#define NBC       32           // B*C

struct __align__(16) Smem {
    float  oa[4][OA_LEN];          // 4 overlap classes (plain stores)   45056 B
    float2 stage[MAXFR * F_BINS];  // staged spectra [t_rel][k]          39064 B
    float2 e512[NFFT];             // e^{+i 2 pi t / 512}                 4096 B
    float  win[NFFT];              // window                              2048 B
};

__device__ __forceinline__ float2 cmul(float2 a, float2 b) {
    return make_float2(a.x * b.x - a.y * b.y, a.x * b.y + a.y * b.x);
}
__device__ __forceinline__ float2 cadd(float2 a, float2 b) {
    return make_float2(a.x + b.x, a.y + b.y);
}
__device__ __forceinline__ float2 csub(float2 a, float2 b) {
    return make_float2(a.x - b.x, a.y - b.y);
}

__global__ void __launch_bounds__(256, 2)
istft_kernel(const float* __restrict__ X,
             const float* __restrict__ window,
             float* __restrict__ out)
{
    extern __shared__ char smraw[];
    Smem& sm = *reinterpret_cast<Smem*>(smraw);

    const int tid  = threadIdx.x;      // 0..255
    const int warp = tid >> 5;         // 0..7
    const int lane = tid & 31;
    const int bc   = blockIdx.y;       // 0..31
    const int o0   = blockIdx.x * CHUNK;

    int t_lo = (o0 - 128) >> 7; if (t_lo < 0) t_lo = 0;
    int t_hi = (o0 + CHUNK + 255) >> 7; if (t_hi > T_FRAMES - 1) t_hi = T_FRAMES - 1;
    const int nt = t_hi - t_lo + 1;    // <= 19

    // ---- tables ----
    for (int i = tid; i < NFFT; i += 256) {
        float s, c;
        sincosf((float)(2.0 * M_PI / NFFT) * (float)i, &s, &c);
        sm.e512[i] = make_float2(c, s);
        sm.win[i]  = window[i];
    }
    // ---- zero overlap-add classes ----
    {
        float4* p = reinterpret_cast<float4*>(&sm.oa[0][0]);
        for (int i = tid; i < 4 * OA_LEN / 4; i += 256)
            p[i] = make_float4(0.f, 0.f, 0.f, 0.f);
    }

    // ---- stage spectra: one warp per k-row, lanes sweep frames (coalesced t) ----
    const float2* Xbc = reinterpret_cast<const float2*>(X)
                        + (size_t)bc * F_BINS * T_FRAMES;
    for (int k = warp; k < F_BINS; k += 8) {
        if (lane < nt)
            sm.stage[lane * F_BINS + k] = Xbc[(size_t)k * T_FRAMES + t_lo + lane];
    }
    __syncthreads();

    // ---- per-lane constants (fixed across frames) ----
    const int n1 = __brev(lane) >> 27;           // bit-reversed lane = output segment
    const float2 w256 = sm.e512[2 * lane];       // e^{+2pi i lane/256}

    float2 twc[5];                               // cross-lane stage twiddles
    #pragma unroll
    for (int s = 0; s < 5; s++) {
        const int h = 16 >> s;
        const int j = lane & (h - 1);
        twc[s] = (lane & h) ? sm.e512[j * (16 << s)] : make_float2(1.f, 0.f);
    }
    float wreg[16];                              // window * 1/256 for my 16 samples
    #pragma unroll
    for (int j = 0; j < 16; j++)
        wreg[j] = sm.win[16 * n1 + j] * (1.0f / 256.0f);

    // ---- frames: warp w handles fr = w, w+8, w+16 -> class buffer (w&3) ----
    float* oacls = sm.oa[warp & 3];

    for (int fr = warp; fr < nt; fr += 8) {
        const float2* spec = &sm.stage[fr * F_BINS];
        float2 z[8];

        // preprocess: Z[k] for k = lane + 32r  (irfft real-packing)
        #pragma unroll
        for (int r = 0; r < 8; r++) {
            const int k = lane + 32 * r;
            float2 a = spec[k];
            float2 b = spec[256 - k];
            if (k == 0) { a.y = 0.f; b.y = 0.f; }
            const float zer = 0.5f * (a.x + b.x);
            const float zei = 0.5f * (a.y - b.y);
            const float tr  = 0.5f * (a.x - b.x);
            const float ti  = 0.5f * (a.y + b.y);
            const float2 w  = sm.e512[k];
            const float zor = w.x * tr - w.y * ti;
            const float zoi = w.x * ti + w.y * tr;
            z[r] = make_float2(zer - zoi, zei + zor);
        }

        // ---- Step A: 8-point IDFT over registers (r -> n2) ----
        {
            const float S = 0.70710678118654752f;
            float2 t0 = cadd(z[0], z[4]), t1 = csub(z[0], z[4]);
            float2 t2 = cadd(z[2], z[6]), t3 = csub(z[2], z[6]);
            float2 E0 = cadd(t0, t2), E2 = csub(t0, t2);
            float2 it3 = make_float2(-t3.y, t3.x);
            float2 E1 = cadd(t1, it3), E3 = csub(t1, it3);

            float2 u0 = cadd(z[1], z[5]), u1 = csub(z[1], z[5]);
            float2 u2 = cadd(z[3], z[7]), u3 = csub(z[3], z[7]);
            float2 O0 = cadd(u0, u2), O2 = csub(u0, u2);
            float2 iu3 = make_float2(-u3.y, u3.x);
            float2 O1 = cadd(u1, iu3), O3 = csub(u1, iu3);

            float2 W1O1 = make_float2(S * (O1.x - O1.y), S * (O1.x + O1.y));  // e^{i pi/4}
            float2 iO2  = make_float2(-O2.y, O2.x);                            // e^{i pi/2}
            float2 W3O3 = make_float2(-S * (O3.x + O3.y), S * (O3.x - O3.y));  // e^{i 3pi/4}

            z[0] = cadd(E0, O0);   z[4] = csub(E0, O0);
            z[1] = cadd(E1, W1O1); z[5] = csub(E1, W1O1);
            z[2] = cadd(E2, iO2);  z[6] = csub(E2, iO2);
            z[3] = cadd(E3, W3O3); z[7] = csub(E3, W3O3);
        }

        // ---- Step B: twiddle W256^{n2 * lane} ----
        {
            float2 t = w256;
            #pragma unroll
            for (int r = 1; r < 8; r++) {
                z[r] = cmul(z[r], t);
                if (r < 7) t = cmul(t, w256);
            }
        }

        // ---- Step C: 32-point IDFT across lanes (5 shfl_xor stages, DIF) ----
        #pragma unroll
        for (int s = 0; s < 5; s++) {
            const int h = 16 >> s;
            const bool hi = (lane & h) != 0;
            const float2 w = twc[s];
            #pragma unroll
            for (int r = 0; r < 8; r++) {
                float2 a = z[r];
                float2 b;
                b.x = __shfl_xor_sync(0xffffffffu, a.x, h);
                b.y = __shfl_xor_sync(0xffffffffu, a.y, h);
                float2 d = hi ? csub(b, a) : cadd(a, b);
                z[r] = cmul(d, w);
            }
        }
        // lane p now holds y[n2 + 8*brev5(p)] in regs n2=0..7;
        // time samples: out[16*n1 + 2*n2]     = Re * win
        //               out[16*n1 + 2*n2 + 1] = Im * win

        // ---- window + plain store (disjoint within class) ----
        float4* dst = reinterpret_cast<float4*>(&oacls[fr * HOP + 16 * n1]);
        #pragma unroll
        for (int q = 0; q < 4; q++) {
            float4 v;
            v.x = z[2 * q].x     * wreg[4 * q];
            v.y = z[2 * q].y     * wreg[4 * q + 1];
            v.z = z[2 * q + 1].x * wreg[4 * q + 2];
            v.w = z[2 * q + 1].y * wreg[4 * q + 3];
            dst[q] = v;
        }
    }

    __syncthreads();

    // ---- envelope normalize + coalesced write ----
    float* outbc = out + (size_t)bc * OUT_LEN;
    const int oabase = t_lo * HOP;
    for (int jj = tid; jj < CHUNK; jj += 256) {
        const int j = o0 + jj;
        if (j >= OUT_LEN) break;
        const int i  = j + NFFT / 2;
        const int r  = i & (HOP - 1);
        const int bt = i >> 7;
        float env = 0.0f;
        #pragma unroll
        for (int s2 = 0; s2 < 4; s2++) {
            const int t = bt - s2;
            if (t >= 0 && t <= T_FRAMES - 1) {
                const float wv = sm.win[r + 128 * s2];
                env += wv * wv;
            }
        }
        const int ii = i - oabase;
        const float v = sm.oa[0][ii] + sm.oa[1][ii] + sm.oa[2][ii] + sm.oa[3][ii];
        outbc[j] = __fdividef(v, env);
    }
}

extern "C" void kernel_launch(void* const* d_in, const int* in_sizes, int n_in,
                              void* d_out, int out_size)
{
    const float* X   = (const float*)d_in[0];
    const float* win = (const float*)d_in[1];
    float* out       = (float*)d_out;

    cudaFuncSetAttribute(istft_kernel,
                         cudaFuncAttributeMaxDynamicSharedMemorySize,
                         (int)sizeof(Smem));

    dim3 grid(OUT_LEN / CHUNK + ((OUT_LEN % CHUNK) ? 1 : 0), NBC);  // (128, 32)
    istft_kernel<<<grid, 256, sizeof(Smem)>>>(X, win, out);
}

// round 4
// speedup vs baseline: 1.1815x; 1.1062x over previous
#include <cuda_runtime.h>
#include <cuda_fp16.h>
#include <math.h>

#define NFFT      512
#define HOP       128
#define T_FRAMES  2048
#define F_BINS    257
#define OUT_LEN   262016       // (T-1)*HOP
#define CHUNK     2048         // output samples per block (= 16 hops)
#define MAXFR     19           // frames touching one chunk
#define OA_LEN    2816         // 128*18 + 512
#define NBC       32           // B*C

struct __align__(16) Smem {
    float   oa[4][OA_LEN];          // 4 overlap classes (plain stores)  45056 B
    __half2 stage[MAXFR * F_BINS];  // staged spectra, fp16              19532 B
    float2  e512[NFFT];             // e^{+i 2 pi t / 512}                4096 B
    float   win[NFFT];              // window                             2048 B
};

__device__ __forceinline__ float2 cmul(float2 a, float2 b) {
    return make_float2(a.x * b.x - a.y * b.y, a.x * b.y + a.y * b.x);
}
__device__ __forceinline__ float2 cadd(float2 a, float2 b) {
    return make_float2(a.x + b.x, a.y + b.y);
}
__device__ __forceinline__ float2 csub(float2 a, float2 b) {
    return make_float2(a.x - b.x, a.y - b.y);
}

__global__ void __launch_bounds__(256, 3)
istft_kernel(const float* __restrict__ X,
             const float* __restrict__ window,
             float* __restrict__ out)
{
    extern __shared__ char smraw[];
    Smem& sm = *reinterpret_cast<Smem*>(smraw);

    const int tid  = threadIdx.x;      // 0..255
    const int warp = tid >> 5;         // 0..7
    const int lane = tid & 31;
    const int bc   = blockIdx.y;       // 0..31
    const int o0   = blockIdx.x * CHUNK;

    int t_lo = (o0 - 128) >> 7; if (t_lo < 0) t_lo = 0;
    int t_hi = (o0 + CHUNK + 255) >> 7; if (t_hi > T_FRAMES - 1) t_hi = T_FRAMES - 1;
    const int nt = t_hi - t_lo + 1;    // <= 19

    // ---- tables ----
    for (int i = tid; i < NFFT; i += 256) {
        float s, c;
        sincosf((float)(2.0 * M_PI / NFFT) * (float)i, &s, &c);
        sm.e512[i] = make_float2(c, s);
        sm.win[i]  = window[i];
    }
    // ---- zero overlap-add classes ----
    {
        float4* p = reinterpret_cast<float4*>(&sm.oa[0][0]);
        for (int i = tid; i < 4 * OA_LEN / 4; i += 256)
            p[i] = make_float4(0.f, 0.f, 0.f, 0.f);
    }

    // ---- stage spectra (fp16): one warp per k-row, lanes sweep frames ----
    const float2* Xbc = reinterpret_cast<const float2*>(X)
                        + (size_t)bc * F_BINS * T_FRAMES;
    for (int k = warp; k < F_BINS; k += 8) {
        if (lane < nt) {
            float2 v = Xbc[(size_t)k * T_FRAMES + t_lo + lane];
            sm.stage[lane * F_BINS + k] = __floats2half2_rn(v.x, v.y);
        }
    }
    __syncthreads();

    const int n1 = __brev(lane) >> 27;   // bit-reversed lane = output segment

    // ---- frames: warp w handles fr = w, w+8, w+16 -> class buffer (w&3) ----
    float* oacls = sm.oa[warp & 3];

    for (int fr = warp; fr < nt; fr += 8) {
        const __half2* spec = &sm.stage[fr * F_BINS];
        float2 z[8];

        // preprocess: Z[k] for k = lane + 32r  (irfft real-packing)
        #pragma unroll
        for (int r = 0; r < 8; r++) {
            const int k = lane + 32 * r;
            float2 a = __half22float2(spec[k]);
            float2 b = __half22float2(spec[256 - k]);
            if (k == 0) { a.y = 0.f; b.y = 0.f; }
            const float zer = 0.5f * (a.x + b.x);
            const float zei = 0.5f * (a.y - b.y);
            const float tr  = 0.5f * (a.x - b.x);
            const float ti  = 0.5f * (a.y + b.y);
            const float2 w  = sm.e512[k];
            const float zor = w.x * tr - w.y * ti;
            const float zoi = w.x * ti + w.y * tr;
            z[r] = make_float2(zer - zoi, zei + zor);
        }

        // ---- Step A: 8-point IDFT over registers (r -> n2) ----
        {
            const float S = 0.70710678118654752f;
            float2 t0 = cadd(z[0], z[4]), t1 = csub(z[0], z[4]);
            float2 t2 = cadd(z[2], z[6]), t3 = csub(z[2], z[6]);
            float2 E0 = cadd(t0, t2), E2 = csub(t0, t2);
            float2 it3 = make_float2(-t3.y, t3.x);
            float2 E1 = cadd(t1, it3), E3 = csub(t1, it3);

            float2 u0 = cadd(z[1], z[5]), u1 = csub(z[1], z[5]);
            float2 u2 = cadd(z[3], z[7]), u3 = csub(z[3], z[7]);
            float2 O0 = cadd(u0, u2), O2 = csub(u0, u2);
            float2 iu3 = make_float2(-u3.y, u3.x);
            float2 O1 = cadd(u1, iu3), O3 = csub(u1, iu3);

            float2 W1O1 = make_float2(S * (O1.x - O1.y), S * (O1.x + O1.y));
            float2 iO2  = make_float2(-O2.y, O2.x);
            float2 W3O3 = make_float2(-S * (O3.x + O3.y), S * (O3.x - O3.y));

            z[0] = cadd(E0, O0);   z[4] = csub(E0, O0);
            z[1] = cadd(E1, W1O1); z[5] = csub(E1, W1O1);
            z[2] = cadd(E2, iO2);  z[6] = csub(E2, iO2);
            z[3] = cadd(E3, W3O3); z[7] = csub(E3, W3O3);
        }

        // ---- Step B: twiddle W256^{n2 * lane} via independent table loads ----
        #pragma unroll
        for (int r = 1; r < 8; r++)
            z[r] = cmul(z[r], sm.e512[(2 * lane * r) & (NFFT - 1)]);

        // ---- Step C: 32-point IDFT across lanes (5 shfl_xor stages, DIF) ----
        #pragma unroll
        for (int s = 0; s < 5; s++) {
            const int h = 16 >> s;
            const bool hi = (lane & h) != 0;
            const int j = lane & (h - 1);
            const float2 w = sm.e512[hi ? j * (16 << s) : 0];  // e512[0] = (1,0)
            #pragma unroll
            for (int r = 0; r < 8; r++) {
                float2 a = z[r];
                float2 b;
                b.x = __shfl_xor_sync(0xffffffffu, a.x, h);
                b.y = __shfl_xor_sync(0xffffffffu, a.y, h);
                float2 d = hi ? csub(b, a) : cadd(a, b);
                z[r] = cmul(d, w);
            }
        }
        // lane p holds y[2*n2 + 16*brev5(p)] (Re) / y[...+1] (Im), n2 = reg

        // ---- window (from smem) + plain store (disjoint within class) ----
        const float4* w4 = reinterpret_cast<const float4*>(&sm.win[16 * n1]);
        float4* dst = reinterpret_cast<float4*>(&oacls[fr * HOP + 16 * n1]);
        #pragma unroll
        for (int q = 0; q < 4; q++) {
            const float4 wq = w4[q];
            float4 v;
            v.x = z[2 * q].x     * wq.x * (1.0f / 256.0f);
            v.y = z[2 * q].y     * wq.y * (1.0f / 256.0f);
            v.z = z[2 * q + 1].x * wq.z * (1.0f / 256.0f);
            v.w = z[2 * q + 1].y * wq.w * (1.0f / 256.0f);
            dst[q] = v;
        }
    }

    __syncthreads();

    // ---- envelope normalize + coalesced write ----
    float* outbc = out + (size_t)bc * OUT_LEN;
    const int oabase = t_lo * HOP;
    for (int jj = tid; jj < CHUNK; jj += 256) {
        const int j = o0 + jj;
        if (j >= OUT_LEN) break;
        const int i  = j + NFFT / 2;
        const int r  = i & (HOP - 1);
        const int bt = i >> 7;
        float env = 0.0f;
        #pragma unroll
        for (int s2 = 0; s2 < 4; s2++) {
            const int t = bt - s2;
            if (t >= 0 && t <= T_FRAMES - 1) {
                const float wv = sm.win[r + 128 * s2];
                env += wv * wv;
            }
        }
        const int ii = i - oabase;
        const float v = sm.oa[0][ii] + sm.oa[1][ii] + sm.oa[2][ii] + sm.oa[3][ii];
        outbc[j] = __fdividef(v, env);
    }
}

extern "C" void kernel_launch(void* const* d_in, const int* in_sizes, int n_in,
                              void* d_out, int out_size)
{
    const float* X   = (const float*)d_in[0];
    const float* win = (const float*)d_in[1];
    float* out       = (float*)d_out;

    cudaFuncSetAttribute(istft_kernel,
                         cudaFuncAttributeMaxDynamicSharedMemorySize,
                         (int)sizeof(Smem));

    dim3 grid(OUT_LEN / CHUNK + ((OUT_LEN % CHUNK) ? 1 : 0), NBC);  // (128, 32)
    istft_kernel<<<grid, 256, sizeof(Smem)>>>(X, win, out);
}